// round 15
// baseline (speedup 1.0000x reference)
#include <cuda_runtime.h>
#include <cuda_fp16.h>
#include <stdint.h>

// Problem geometry: image (32,3,512,512) f32; noise subbands (32,3,256,256) x4.
#define N_NOISE  6291456      // 32*3*256*256
#define N_PAIRS  3145728      // N_NOISE / 2
#define HALF_P   1572864      // N_PAIRS / 2
#define N_TOTAL  25165824     // 32*3*512*512
#define LO_F     (-0.99999994f)   // np.nextafter(-1, 0) in f32

// Scratch (static __device__ allocation allowed; cudaMalloc is not)
// Quad-major noise: entry p holds {LL,LH,HL,HH} for quads 2p,2p+1 as 4x half2.
__device__ uint4    g_noise_q[N_PAIRS];        // ~50.3 MB; L2-resident k_noise->k_enc
__device__ __half   g_enc_h[N_TOTAL];          // ~50.3 MB; L2-resident k_enc->k_out
__device__ unsigned g_maxbits[4];              // zero-init = identity for atomicMax
__device__ unsigned g_bmin[32] = {             // identity for atomicMin (order-preserving enc)
    0xFFFFFFFFu,0xFFFFFFFFu,0xFFFFFFFFu,0xFFFFFFFFu,0xFFFFFFFFu,0xFFFFFFFFu,0xFFFFFFFFu,0xFFFFFFFFu,
    0xFFFFFFFFu,0xFFFFFFFFu,0xFFFFFFFFu,0xFFFFFFFFu,0xFFFFFFFFu,0xFFFFFFFFu,0xFFFFFFFFu,0xFFFFFFFFu,
    0xFFFFFFFFu,0xFFFFFFFFu,0xFFFFFFFFu,0xFFFFFFFFu,0xFFFFFFFFu,0xFFFFFFFFu,0xFFFFFFFFu,0xFFFFFFFFu,
    0xFFFFFFFFu,0xFFFFFFFFu,0xFFFFFFFFu,0xFFFFFFFFu,0xFFFFFFFFu,0xFFFFFFFFu,0xFFFFFFFFu,0xFFFFFFFFu};
__device__ unsigned g_bmax[32];                // zero-init = identity for atomicMax

__device__ __forceinline__ unsigned h2_bits(__half2 h) {
    return *reinterpret_cast<unsigned*>(&h);
}

// single-instruction full-warp reductions (REDUX)
__device__ __forceinline__ unsigned redux_max_u32(unsigned v) {
    unsigned r;
    asm("redux.sync.max.u32 %0, %1, 0xffffffff;" : "=r"(r) : "r"(v));
    return r;
}
__device__ __forceinline__ unsigned redux_min_u32(unsigned v) {
    unsigned r;
    asm("redux.sync.min.u32 %0, %1, 0xffffffff;" : "=r"(r) : "r"(v));
    return r;
}

// ---------------- Threefry-2x32 (exactly JAX's schedule) ----------------
__host__ __device__ __forceinline__ void tf2x32(unsigned k0, unsigned k1,
                                                unsigned x0, unsigned x1,
                                                unsigned &o0, unsigned &o1) {
    unsigned ks2 = k0 ^ k1 ^ 0x1BD11BDAu;
    x0 += k0; x1 += k1;
#if defined(__CUDA_ARCH__)
#define ROTL(x, r) __funnelshift_l((x), (x), (r))
#else
#define ROTL(x, r) (((x) << (r)) | ((x) >> (32 - (r))))
#endif
#define TFR(r) { x0 += x1; x1 = ROTL(x1, r); x1 ^= x0; }
    TFR(13) TFR(15) TFR(26) TFR(6)
    x0 += k1;  x1 += ks2 + 1u;
    TFR(17) TFR(29) TFR(16) TFR(24)
    x0 += ks2; x1 += k0 + 2u;
    TFR(13) TFR(15) TFR(26) TFR(6)
    x0 += k0;  x1 += k1 + 3u;
    TFR(17) TFR(29) TFR(16) TFR(24)
    x0 += k1;  x1 += ks2 + 4u;
    TFR(13) TFR(15) TFR(26) TFR(6)
    x0 += ks2; x1 += k0 + 5u;
#undef TFR
#undef ROTL
    o0 = x0; o1 = x1;
}

// ---------------- erf_inv (Giles polynomial; fast-log variant, branchy) --------
__device__ __forceinline__ float erfinv_fast(float x) {
    float w = -__logf(fmaf(-x, x, 1.0f));
    float p;
    if (w < 5.0f) {
        w = w - 2.5f;
        p =                2.81022636e-08f;
        p = fmaf(p, w,     3.43273939e-07f);
        p = fmaf(p, w,    -3.5233877e-06f);
        p = fmaf(p, w,    -4.39150654e-06f);
        p = fmaf(p, w,     0.00021858087f);
        p = fmaf(p, w,    -0.00125372503f);
        p = fmaf(p, w,    -0.00417768164f);
        p = fmaf(p, w,     0.246640727f);
        p = fmaf(p, w,     1.50140941f);
    } else {
        w = sqrtf(w) - 3.0f;
        p =               -0.000200214257f;
        p = fmaf(p, w,     0.000100950558f);
        p = fmaf(p, w,     0.00134934322f);
        p = fmaf(p, w,    -0.00367342844f);
        p = fmaf(p, w,     0.00573950773f);
        p = fmaf(p, w,    -0.0076224613f);
        p = fmaf(p, w,     0.00943887047f);
        p = fmaf(p, w,     1.00167406f);
        p = fmaf(p, w,     2.83297682f);
    }
    return p * x;
}

// Order-preserving float<->uint encoding for signed min/max atomics
__device__ __forceinline__ unsigned fenc(float f) {
    unsigned u = __float_as_uint(f);
    return (u & 0x80000000u) ? ~u : (u | 0x80000000u);
}
__device__ __forceinline__ float fdec(unsigned u) {
    return __uint_as_float((u & 0x80000000u) ? (u ^ 0x80000000u) : ~u);
}

// one sample: counter i -> N(0,1) float
__device__ __forceinline__ float sample_normal(unsigned kk0, unsigned kk1, unsigned i) {
    unsigned o0, o1;
    tf2x32(kk0, kk1, 0u, i, o0, o1);
    unsigned bits = o0 ^ o1;
    unsigned mant = __umulhi(bits, 0x00800000u);           // == bits >> 9, fma pipe
    float g = __uint_as_float(mant | 0x3F800000u);         // [1,2)
    // u = 2(g-1) + LO_F, fused: fl(LO_F - 2) == -3.0f (drift ~6e-8, harmless)
    float u = fmaf(g, 2.0f, -3.0f);
    u = fmaxf(u, LO_F);
    return 1.41421356237f * erfinv_fast(u);
}

// thread->geometry mapping shared by k_noise / k_enc (pair p = quads 2p, 2p+1)
__device__ __forceinline__ size_t pair_ibase(unsigned p) {
    unsigned q0 = p * 2u;
    unsigned wh0 = q0 & 255u;
    unsigned hh  = (q0 >> 8) & 255u;
    unsigned pl  = q0 >> 16;
    return (size_t)pl * 262144u + (size_t)hh * 1024u + (size_t)wh0 * 2u;
}

// ---------------- K1: noise gen (quad-major, 8 samples/thread) + subband maxes --
// grid 12288 x 256; thread p covers quads 2p, 2p+1 across all 4 subbands.
// No img warm loads: keeps k_noise's L2 footprint = noise only (50 MB < 126 MB),
// so the noise survives to k_enc and never round-trips DRAM.
__global__ void __launch_bounds__(256) k_noise(uint4 keyA, uint4 keyB) {
    unsigned p  = blockIdx.x * 256u + threadIdx.x;
    unsigned q0 = p * 2u;

    // ---- 8 independent threefry chains ----
    float nLL0 = sample_normal(keyA.x, keyA.y, q0);
    float nLL1 = sample_normal(keyA.x, keyA.y, q0 + 1u);
    float nLH0 = sample_normal(keyA.z, keyA.w, q0);
    float nLH1 = sample_normal(keyA.z, keyA.w, q0 + 1u);
    float nHL0 = sample_normal(keyB.x, keyB.y, q0);
    float nHL1 = sample_normal(keyB.x, keyB.y, q0 + 1u);
    float nHH0 = sample_normal(keyB.z, keyB.w, q0);
    float nHH1 = sample_normal(keyB.z, keyB.w, q0 + 1u);

    g_noise_q[p] = make_uint4(h2_bits(__floats2half2_rn(nLL0, nLL1)),
                              h2_bits(__floats2half2_rn(nLH0, nLH1)),
                              h2_bits(__floats2half2_rn(nHL0, nHL1)),
                              h2_bits(__floats2half2_rn(nHH0, nHH1)));

    // ---- per-subband max|n|: nonneg f32 bits are monotonic -> REDUX on uint ----
    unsigned m0 = redux_max_u32(__float_as_uint(fmaxf(fabsf(nLL0), fabsf(nLL1))));
    unsigned m1 = redux_max_u32(__float_as_uint(fmaxf(fabsf(nLH0), fabsf(nLH1))));
    unsigned m2 = redux_max_u32(__float_as_uint(fmaxf(fabsf(nHL0), fabsf(nHL1))));
    unsigned m3 = redux_max_u32(__float_as_uint(fmaxf(fabsf(nHH0), fabsf(nHH1))));

    __shared__ unsigned smx[8][4];
    int w = threadIdx.x >> 5, l = threadIdx.x & 31;
    if (l == 0) { smx[w][0] = m0; smx[w][1] = m1; smx[w][2] = m2; smx[w][3] = m3; }
    __syncthreads();
    if (threadIdx.x < 4) {
        unsigned m = smx[0][threadIdx.x];
#pragma unroll
        for (int j = 1; j < 8; ++j) m = max(m, smx[j][threadIdx.x]);
        atomicMax(&g_maxbits[threadIdx.x], m);
    }
}

// compute the 8 enc values for one pair; returns min/max through refs
__device__ __forceinline__ void enc_pair(const float* __restrict__ img,
                                         unsigned p, uint4 nv,
                                         float iLL, float iLH, float iHL, float iHH,
                                         float &lmin, float &lmax) {
    size_t ibase = pair_ibase(p);
    float2 LL = __half22float2(*reinterpret_cast<__half2*>(&nv.x));
    float2 LH = __half22float2(*reinterpret_cast<__half2*>(&nv.y));
    float2 HL = __half22float2(*reinterpret_cast<__half2*>(&nv.z));
    float2 HH = __half22float2(*reinterpret_cast<__half2*>(&nv.w));

    float4 i0 = *reinterpret_cast<const float4*>(img + ibase);          // a0 b0 a1 b1
    float4 i1 = *reinterpret_cast<const float4*>(img + ibase + 512u);   // c0 d0 c1 d1

    float4 r0, r1;
    {
        float nLL = LL.x * iLL, nLH = LH.x * iLH, nHL = HL.x * iHL, nHH = HH.x * iHH;
        float s0 = nLL + nLH, s1 = nHL + nHH;
        float d0 = nLL - nLH, d1 = nHL - nHH;
        r0.x = i0.x + (s0 + s1) * 0.5f;
        r0.y = i0.y + (s0 - s1) * 0.5f;
        r1.x = i1.x + (d0 + d1) * 0.5f;
        r1.y = i1.y + (d0 - d1) * 0.5f;
    }
    {
        float nLL = LL.y * iLL, nLH = LH.y * iLH, nHL = HL.y * iHL, nHH = HH.y * iHH;
        float s0 = nLL + nLH, s1 = nHL + nHH;
        float d0 = nLL - nLH, d1 = nHL - nHH;
        r0.z = i0.z + (s0 + s1) * 0.5f;
        r0.w = i0.w + (s0 - s1) * 0.5f;
        r1.z = i1.z + (d0 + d1) * 0.5f;
        r1.w = i1.w + (d0 - d1) * 0.5f;
    }

    *reinterpret_cast<uint2*>(g_enc_h + ibase) =
        make_uint2(h2_bits(__floats2half2_rn(r0.x, r0.y)),
                   h2_bits(__floats2half2_rn(r0.z, r0.w)));
    *reinterpret_cast<uint2*>(g_enc_h + ibase + 512u) =
        make_uint2(h2_bits(__floats2half2_rn(r1.x, r1.y)),
                   h2_bits(__floats2half2_rn(r1.z, r1.w)));

    lmin = fminf(fminf(fminf(r0.x, r0.y), fminf(r0.z, r0.w)),
                 fminf(fminf(r1.x, r1.y), fminf(r1.z, r1.w)));
    lmax = fmaxf(fmaxf(fmaxf(r0.x, r0.y), fmaxf(r0.z, r0.w)),
                 fmaxf(fmaxf(r1.x, r1.y), fmaxf(r1.z, r1.w)));
}

// ---------------- K2: enc = img + idwt(noise/max); 2 pairs/thread (MLP=2) -------
// grid 6144 x 256. Thread t handles pairs t and t+HALF_P (batches b and b+16).
__global__ void __launch_bounds__(256) k_enc(const float* __restrict__ img) {
    unsigned t  = blockIdx.x * 256u + threadIdx.x;   // 0 .. HALF_P-1
    unsigned pA = t, pB = t + HALF_P;

    float iLL = 1.0f / (__uint_as_float(g_maxbits[0]) + 1e-8f);
    float iLH = 1.0f / (__uint_as_float(g_maxbits[1]) + 1e-8f);
    float iHL = 1.0f / (__uint_as_float(g_maxbits[2]) + 1e-8f);
    float iHH = 1.0f / (__uint_as_float(g_maxbits[3]) + 1e-8f);

    // issue both noise loads first (last use: streaming)
    uint4 nvA = __ldcs(&g_noise_q[pA]);
    uint4 nvB = __ldcs(&g_noise_q[pB]);

    float mnA, mxA, mnB, mxB;
    enc_pair(img, pA, nvA, iLL, iLH, iHL, iHH, mnA, mxA);
    enc_pair(img, pB, nvB, iLL, iLH, iHL, iHH, mnB, mxB);

    // warp reduction via REDUX on order-preserving encodings
    unsigned eMnA = redux_min_u32(fenc(mnA));
    unsigned eMxA = redux_max_u32(fenc(mxA));
    unsigned eMnB = redux_min_u32(fenc(mnB));
    unsigned eMxB = redux_max_u32(fenc(mxB));

    __shared__ unsigned smnA[8], smxA[8], smnB[8], smxB[8];
    int w = threadIdx.x >> 5, l = threadIdx.x & 31;
    if (l == 0) { smnA[w] = eMnA; smxA[w] = eMxA; smnB[w] = eMnB; smxB[w] = eMxB; }
    __syncthreads();
    if (threadIdx.x == 0) {
        unsigned mnAa = smnA[0], mxAa = smxA[0], mnBa = smnB[0], mxBa = smxB[0];
#pragma unroll
        for (int j = 1; j < 8; ++j) {
            mnAa = min(mnAa, smnA[j]); mxAa = max(mxAa, smxA[j]);
            mnBa = min(mnBa, smnB[j]); mxBa = max(mxBa, smxB[j]);
        }
        // 384 blocks per batch for the A range (98304 pairs/batch / 256)
        int bA = (int)(blockIdx.x / 384u);
        int bB = bA + 16;
        atomicMin(&g_bmin[bA], mnAa);
        atomicMax(&g_bmax[bA], mxAa);
        atomicMin(&g_bmin[bB], mnBa);
        atomicMax(&g_bmax[bB], mxBa);
    }
}

// ---------------- K3: out = (enc_h - min) * inv ; 2 float4 per thread (MLP=2) ----
__global__ void __launch_bounds__(256) k_out(float* __restrict__ out) {
    unsigned i = blockIdx.x * 256u + threadIdx.x;    // 0 .. 3145727
    const unsigned HALF = 3145728u;                  // float4 count / 2

    unsigned iA = i, iB = i + HALF;
    // 196608 float4 per batch
    int bA = (int)(iA / 196608u);
    int bB = bA + 16;

    uint2 hA = *reinterpret_cast<const uint2*>(g_enc_h + (size_t)iA * 4u);
    uint2 hB = *reinterpret_cast<const uint2*>(g_enc_h + (size_t)iB * 4u);

    float mnA = fdec(g_bmin[bA]), mxA = fdec(g_bmax[bA]);
    float invA = 1.0f / fmaxf(mxA - mnA, 1e-8f);
    float mnB = fdec(g_bmin[bB]), mxB = fdec(g_bmax[bB]);
    float invB = 1.0f / fmaxf(mxB - mnB, 1e-8f);

    float2 fA01 = __half22float2(*reinterpret_cast<__half2*>(&hA.x));
    float2 fA23 = __half22float2(*reinterpret_cast<__half2*>(&hA.y));
    float2 fB01 = __half22float2(*reinterpret_cast<__half2*>(&hB.x));
    float2 fB23 = __half22float2(*reinterpret_cast<__half2*>(&hB.y));

    float4 rA, rB;
    rA.x = (fA01.x - mnA) * invA;  rA.y = (fA01.y - mnA) * invA;
    rA.z = (fA23.x - mnA) * invA;  rA.w = (fA23.y - mnA) * invA;
    rB.x = (fB01.x - mnB) * invB;  rB.y = (fB01.y - mnB) * invB;
    rB.z = (fB23.x - mnB) * invB;  rB.w = (fB23.y - mnB) * invB;

    __stcs(reinterpret_cast<float4*>(out) + iA, rA);   // streaming store
    __stcs(reinterpret_cast<float4*>(out) + iB, rB);
}

extern "C" void kernel_launch(void* const* d_in, const int* in_sizes, int n_in,
                              void* d_out, int out_size) {
    const float* img = (const float*)d_in[0];
    float* out = (float*)d_out;

    // jax.random.split(jax.random.key(123), 4), threefry_partitionable
    unsigned keys[8];
    for (unsigned t = 0; t < 4; ++t) {
        unsigned o0, o1;
        tf2x32(0u, 123u, 0u, t, o0, o1);
        keys[2 * t] = o0; keys[2 * t + 1] = o1;
    }
    uint4 keyA = make_uint4(keys[0], keys[1], keys[2], keys[3]);
    uint4 keyB = make_uint4(keys[4], keys[5], keys[6], keys[7]);

    k_noise<<<12288, 256>>>(keyA, keyB);
    k_enc<<<6144, 256>>>(img);
    k_out<<<12288, 256>>>(out);
}

// round 16
// speedup vs baseline: 1.3944x; 1.3944x over previous
#include <cuda_runtime.h>
#include <cuda_fp16.h>
#include <stdint.h>

// Problem geometry: image (32,3,512,512) f32; noise subbands (32,3,256,256) x4.
#define N_NOISE  6291456      // 32*3*256*256
#define N_PAIRS  3145728      // N_NOISE / 2
#define N_TOTAL  25165824     // 32*3*512*512
#define LO_F     (-0.99999994f)   // np.nextafter(-1, 0) in f32

// Scratch (static __device__ allocation allowed; cudaMalloc is not)
// Quad-major noise: entry p holds {LL,LH,HL,HH} for quads 2p,2p+1 as 4x half2.
__device__ uint4    g_noise_q[N_PAIRS];        // ~50.3 MB, dead after k_enc
__device__ __half   g_enc_h[N_TOTAL];          // ~50.3 MB, L2-resident k_enc->k_out
__device__ unsigned g_maxbits[4];              // zero-init = identity for atomicMax
__device__ unsigned g_bmin[32] = {             // identity for atomicMin (order-preserving enc)
    0xFFFFFFFFu,0xFFFFFFFFu,0xFFFFFFFFu,0xFFFFFFFFu,0xFFFFFFFFu,0xFFFFFFFFu,0xFFFFFFFFu,0xFFFFFFFFu,
    0xFFFFFFFFu,0xFFFFFFFFu,0xFFFFFFFFu,0xFFFFFFFFu,0xFFFFFFFFu,0xFFFFFFFFu,0xFFFFFFFFu,0xFFFFFFFFu,
    0xFFFFFFFFu,0xFFFFFFFFu,0xFFFFFFFFu,0xFFFFFFFFu,0xFFFFFFFFu,0xFFFFFFFFu,0xFFFFFFFFu,0xFFFFFFFFu,
    0xFFFFFFFFu,0xFFFFFFFFu,0xFFFFFFFFu,0xFFFFFFFFu,0xFFFFFFFFu,0xFFFFFFFFu,0xFFFFFFFFu,0xFFFFFFFFu};
__device__ unsigned g_bmax[32];                // zero-init = identity for atomicMax
__device__ unsigned g_dummy;                   // sink for img warm loads

__device__ __forceinline__ unsigned h2_bits(__half2 h) {
    return *reinterpret_cast<unsigned*>(&h);
}

// single-instruction full-warp max reduction (REDUX); nonneg f32 bits monotonic
__device__ __forceinline__ unsigned redux_max_u32(unsigned v) {
    unsigned r;
    asm("redux.sync.max.u32 %0, %1, 0xffffffff;" : "=r"(r) : "r"(v));
    return r;
}

// ---------------- Threefry-2x32 (exactly JAX's schedule) ----------------
__host__ __device__ __forceinline__ void tf2x32(unsigned k0, unsigned k1,
                                                unsigned x0, unsigned x1,
                                                unsigned &o0, unsigned &o1) {
    unsigned ks2 = k0 ^ k1 ^ 0x1BD11BDAu;
    x0 += k0; x1 += k1;
#if defined(__CUDA_ARCH__)
#define ROTL(x, r) __funnelshift_l((x), (x), (r))
#else
#define ROTL(x, r) (((x) << (r)) | ((x) >> (32 - (r))))
#endif
#define TFR(r) { x0 += x1; x1 = ROTL(x1, r); x1 ^= x0; }
    TFR(13) TFR(15) TFR(26) TFR(6)
    x0 += k1;  x1 += ks2 + 1u;
    TFR(17) TFR(29) TFR(16) TFR(24)
    x0 += ks2; x1 += k0 + 2u;
    TFR(13) TFR(15) TFR(26) TFR(6)
    x0 += k0;  x1 += k1 + 3u;
    TFR(17) TFR(29) TFR(16) TFR(24)
    x0 += k1;  x1 += ks2 + 4u;
    TFR(13) TFR(15) TFR(26) TFR(6)
    x0 += ks2; x1 += k0 + 5u;
#undef TFR
#undef ROTL
    o0 = x0; o1 = x1;
}

// ---------------- erf_inv (Giles polynomial; fast-log variant, branchy) --------
__device__ __forceinline__ float erfinv_fast(float x) {
    float w = -__logf(fmaf(-x, x, 1.0f));
    float p;
    if (w < 5.0f) {
        w = w - 2.5f;
        p =                2.81022636e-08f;
        p = fmaf(p, w,     3.43273939e-07f);
        p = fmaf(p, w,    -3.5233877e-06f);
        p = fmaf(p, w,    -4.39150654e-06f);
        p = fmaf(p, w,     0.00021858087f);
        p = fmaf(p, w,    -0.00125372503f);
        p = fmaf(p, w,    -0.00417768164f);
        p = fmaf(p, w,     0.246640727f);
        p = fmaf(p, w,     1.50140941f);
    } else {
        w = sqrtf(w) - 3.0f;
        p =               -0.000200214257f;
        p = fmaf(p, w,     0.000100950558f);
        p = fmaf(p, w,     0.00134934322f);
        p = fmaf(p, w,    -0.00367342844f);
        p = fmaf(p, w,     0.00573950773f);
        p = fmaf(p, w,    -0.0076224613f);
        p = fmaf(p, w,     0.00943887047f);
        p = fmaf(p, w,     1.00167406f);
        p = fmaf(p, w,     2.83297682f);
    }
    return p * x;
}

// Order-preserving float<->uint encoding for signed min/max atomics
__device__ __forceinline__ unsigned fenc(float f) {
    unsigned u = __float_as_uint(f);
    return (u & 0x80000000u) ? ~u : (u | 0x80000000u);
}
__device__ __forceinline__ float fdec(unsigned u) {
    return __uint_as_float((u & 0x80000000u) ? (u ^ 0x80000000u) : ~u);
}

// one sample: counter i -> N(0,1) float (R14-exact math)
__device__ __forceinline__ float sample_normal(unsigned kk0, unsigned kk1, unsigned i) {
    unsigned o0, o1;
    tf2x32(kk0, kk1, 0u, i, o0, o1);
    unsigned bits = o0 ^ o1;
    unsigned mant = __umulhi(bits, 0x00800000u);           // == bits >> 9, fma pipe
    float f = __uint_as_float(mant | 0x3F800000u) - 1.0f;  // [0,1)
    float u = fmaf(f, 2.0f, LO_F);
    u = fmaxf(u, LO_F);
    return 1.41421356237f * erfinv_fast(u);
}

// thread->geometry mapping shared by k_noise / k_enc (pair p = quads 2p, 2p+1)
__device__ __forceinline__ size_t pair_ibase(unsigned p, unsigned &pl) {
    unsigned q0 = p * 2u;
    unsigned wh0 = q0 & 255u;
    unsigned hh  = (q0 >> 8) & 255u;
    pl  = q0 >> 16;
    return (size_t)pl * 262144u + (size_t)hh * 1024u + (size_t)wh0 * 2u;
}

// ---------------- K1: noise gen (quad-major, 8 samples/thread) + maxes + img warm
// grid 12288 x 256; thread p covers quads 2p, 2p+1 across all 4 subbands.
// Warm loads kept: they anchor the 32-reg schedule preserving 8-chain ILP
// (R15 showed dropping them collapses ptxas into a serialized low-reg schedule).
__global__ void __launch_bounds__(256) k_noise(const float* __restrict__ img,
                                               uint4 keyA, uint4 keyB) {
    unsigned p  = blockIdx.x * 256u + threadIdx.x;
    unsigned q0 = p * 2u;

    // ---- img L2 warm: issue loads first (latency hidden by 8 threefry chains) ----
    unsigned pl_;
    size_t ibase = pair_ibase(p, pl_);
    float4 w0 = *reinterpret_cast<const float4*>(img + ibase);
    float4 w1 = *reinterpret_cast<const float4*>(img + ibase + 512u);

    // ---- 8 independent threefry chains ----
    float nLL0 = sample_normal(keyA.x, keyA.y, q0);
    float nLL1 = sample_normal(keyA.x, keyA.y, q0 + 1u);
    float nLH0 = sample_normal(keyA.z, keyA.w, q0);
    float nLH1 = sample_normal(keyA.z, keyA.w, q0 + 1u);
    float nHL0 = sample_normal(keyB.x, keyB.y, q0);
    float nHL1 = sample_normal(keyB.x, keyB.y, q0 + 1u);
    float nHH0 = sample_normal(keyB.z, keyB.w, q0);
    float nHH1 = sample_normal(keyB.z, keyB.w, q0 + 1u);

    g_noise_q[p] = make_uint4(h2_bits(__floats2half2_rn(nLL0, nLL1)),
                              h2_bits(__floats2half2_rn(nLH0, nLH1)),
                              h2_bits(__floats2half2_rn(nHL0, nHL1)),
                              h2_bits(__floats2half2_rn(nHH0, nHH1)));

    // consume warm loads with a data-dependent never-taken store (keeps LDGs live)
    float ws = (w0.x + w0.y + w0.z + w0.w) + (w1.x + w1.y + w1.z + w1.w);
    if (__float_as_uint(ws) == 0xDEADBEEFu) g_dummy = 0u;

    // ---- per-subband max|n| via single-instruction REDUX (uint bits monotonic) --
    unsigned m0 = redux_max_u32(__float_as_uint(fmaxf(fabsf(nLL0), fabsf(nLL1))));
    unsigned m1 = redux_max_u32(__float_as_uint(fmaxf(fabsf(nLH0), fabsf(nLH1))));
    unsigned m2 = redux_max_u32(__float_as_uint(fmaxf(fabsf(nHL0), fabsf(nHL1))));
    unsigned m3 = redux_max_u32(__float_as_uint(fmaxf(fabsf(nHH0), fabsf(nHH1))));

    __shared__ unsigned smx[8][4];
    int w = threadIdx.x >> 5, l = threadIdx.x & 31;
    if (l == 0) { smx[w][0] = m0; smx[w][1] = m1; smx[w][2] = m2; smx[w][3] = m3; }
    __syncthreads();
    if (threadIdx.x < 4) {
        unsigned m = smx[0][threadIdx.x];
#pragma unroll
        for (int j = 1; j < 8; ++j) m = max(m, smx[j][threadIdx.x]);
        atomicMax(&g_maxbits[threadIdx.x], m);
    }
}

// ---------------- K2: enc = img + idwt(noise/max); store enc fp16; batch min/max
// grid 12288 x 256; same pair mapping. (R14-exact)
__global__ void __launch_bounds__(256) k_enc(const float* __restrict__ img) {
    unsigned p = blockIdx.x * 256u + threadIdx.x;
    unsigned pl;
    size_t ibase = pair_ibase(p, pl);

    float iLL = 1.0f / (__uint_as_float(g_maxbits[0]) + 1e-8f);
    float iLH = 1.0f / (__uint_as_float(g_maxbits[1]) + 1e-8f);
    float iHL = 1.0f / (__uint_as_float(g_maxbits[2]) + 1e-8f);
    float iHH = 1.0f / (__uint_as_float(g_maxbits[3]) + 1e-8f);

    uint4 nv = __ldcs(&g_noise_q[p]);      // last use: streaming load, evicts early
    float2 LL = __half22float2(*reinterpret_cast<__half2*>(&nv.x));
    float2 LH = __half22float2(*reinterpret_cast<__half2*>(&nv.y));
    float2 HL = __half22float2(*reinterpret_cast<__half2*>(&nv.z));
    float2 HH = __half22float2(*reinterpret_cast<__half2*>(&nv.w));

    float4 i0 = *reinterpret_cast<const float4*>(img + ibase);          // a0 b0 a1 b1
    float4 i1 = *reinterpret_cast<const float4*>(img + ibase + 512u);   // c0 d0 c1 d1

    float4 r0, r1;
    {
        float nLL = LL.x * iLL, nLH = LH.x * iLH, nHL = HL.x * iHL, nHH = HH.x * iHH;
        float s0 = nLL + nLH, s1 = nHL + nHH;
        float d0 = nLL - nLH, d1 = nHL - nHH;
        r0.x = i0.x + (s0 + s1) * 0.5f;
        r0.y = i0.y + (s0 - s1) * 0.5f;
        r1.x = i1.x + (d0 + d1) * 0.5f;
        r1.y = i1.y + (d0 - d1) * 0.5f;
    }
    {
        float nLL = LL.y * iLL, nLH = LH.y * iLH, nHL = HL.y * iHL, nHH = HH.y * iHH;
        float s0 = nLL + nLH, s1 = nHL + nHH;
        float d0 = nLL - nLH, d1 = nHL - nHH;
        r0.z = i0.z + (s0 + s1) * 0.5f;
        r0.w = i0.w + (s0 - s1) * 0.5f;
        r1.z = i1.z + (d0 + d1) * 0.5f;
        r1.w = i1.w + (d0 - d1) * 0.5f;
    }

    *reinterpret_cast<uint2*>(g_enc_h + ibase) =
        make_uint2(h2_bits(__floats2half2_rn(r0.x, r0.y)),
                   h2_bits(__floats2half2_rn(r0.z, r0.w)));
    *reinterpret_cast<uint2*>(g_enc_h + ibase + 512u) =
        make_uint2(h2_bits(__floats2half2_rn(r1.x, r1.y)),
                   h2_bits(__floats2half2_rn(r1.z, r1.w)));

    float lmin = fminf(fminf(fminf(r0.x, r0.y), fminf(r0.z, r0.w)),
                       fminf(fminf(r1.x, r1.y), fminf(r1.z, r1.w)));
    float lmax = fmaxf(fmaxf(fmaxf(r0.x, r0.y), fmaxf(r0.z, r0.w)),
                       fmaxf(fmaxf(r1.x, r1.y), fmaxf(r1.z, r1.w)));
#pragma unroll
    for (int off = 16; off; off >>= 1) {
        lmin = fminf(lmin, __shfl_xor_sync(0xFFFFFFFFu, lmin, off));
        lmax = fmaxf(lmax, __shfl_xor_sync(0xFFFFFFFFu, lmax, off));
    }
    __shared__ float smn[8], smx[8];
    int w = threadIdx.x >> 5, l = threadIdx.x & 31;
    if (l == 0) { smn[w] = lmin; smx[w] = lmax; }
    __syncthreads();
    if (threadIdx.x == 0) {
        float mn = smn[0], mx = smx[0];
#pragma unroll
        for (int j = 1; j < 8; ++j) { mn = fminf(mn, smn[j]); mx = fmaxf(mx, smx[j]); }
        int b = (int)(blockIdx.x / 384u);   // 128 blocks/plane * 3 planes/batch
        atomicMin(&g_bmin[b], fenc(mn));
        atomicMax(&g_bmax[b], fenc(mx));
    }
}

// ---------------- K3: out = (enc_h - min) * inv ; 2 float4 per thread (MLP=2) ----
__global__ void __launch_bounds__(256) k_out(float* __restrict__ out) {
    unsigned i = blockIdx.x * 256u + threadIdx.x;    // 0 .. 3145727
    const unsigned HALF = 3145728u;                  // float4 count / 2

    unsigned iA = i, iB = i + HALF;
    // 196608 float4 per batch
    int bA = (int)(iA / 196608u);
    int bB = bA + 16;

    uint2 hA = *reinterpret_cast<const uint2*>(g_enc_h + (size_t)iA * 4u);
    uint2 hB = *reinterpret_cast<const uint2*>(g_enc_h + (size_t)iB * 4u);

    float mnA = fdec(g_bmin[bA]), mxA = fdec(g_bmax[bA]);
    float invA = 1.0f / fmaxf(mxA - mnA, 1e-8f);
    float mnB = fdec(g_bmin[bB]), mxB = fdec(g_bmax[bB]);
    float invB = 1.0f / fmaxf(mxB - mnB, 1e-8f);

    float2 fA01 = __half22float2(*reinterpret_cast<__half2*>(&hA.x));
    float2 fA23 = __half22float2(*reinterpret_cast<__half2*>(&hA.y));
    float2 fB01 = __half22float2(*reinterpret_cast<__half2*>(&hB.x));
    float2 fB23 = __half22float2(*reinterpret_cast<__half2*>(&hB.y));

    float4 rA, rB;
    rA.x = (fA01.x - mnA) * invA;  rA.y = (fA01.y - mnA) * invA;
    rA.z = (fA23.x - mnA) * invA;  rA.w = (fA23.y - mnA) * invA;
    rB.x = (fB01.x - mnB) * invB;  rB.y = (fB01.y - mnB) * invB;
    rB.z = (fB23.x - mnB) * invB;  rB.w = (fB23.y - mnB) * invB;

    __stcs(reinterpret_cast<float4*>(out) + iA, rA);   // streaming store
    __stcs(reinterpret_cast<float4*>(out) + iB, rB);
}

extern "C" void kernel_launch(void* const* d_in, const int* in_sizes, int n_in,
                              void* d_out, int out_size) {
    const float* img = (const float*)d_in[0];
    float* out = (float*)d_out;

    // jax.random.split(jax.random.key(123), 4), threefry_partitionable
    unsigned keys[8];
    for (unsigned t = 0; t < 4; ++t) {
        unsigned o0, o1;
        tf2x32(0u, 123u, 0u, t, o0, o1);
        keys[2 * t] = o0; keys[2 * t + 1] = o1;
    }
    uint4 keyA = make_uint4(keys[0], keys[1], keys[2], keys[3]);
    uint4 keyB = make_uint4(keys[4], keys[5], keys[6], keys[7]);

    k_noise<<<12288, 256>>>(img, keyA, keyB);
    k_enc<<<12288, 256>>>(img);
    k_out<<<12288, 256>>>(out);
}

// round 17
// speedup vs baseline: 1.4512x; 1.0408x over previous
#include <cuda_runtime.h>
#include <cuda_fp16.h>
#include <stdint.h>

// Problem geometry: image (32,3,512,512) f32; noise subbands (32,3,256,256) x4.
#define N_NOISE  6291456      // 32*3*256*256
#define N_PAIRS  3145728      // N_NOISE / 2
#define HALF_P   1572864      // N_PAIRS / 2
#define N_TOTAL  25165824     // 32*3*512*512
#define LO_F     (-0.99999994f)   // np.nextafter(-1, 0) in f32

// Scratch (static __device__ allocation allowed; cudaMalloc is not)
// Quad-major noise: entry p holds {LL,LH,HL,HH} for quads 2p,2p+1 as 4x half2.
__device__ uint4    g_noise_q[N_PAIRS];        // ~50.3 MB, dead after k_enc
__device__ __half   g_enc_h[N_TOTAL];          // ~50.3 MB, L2-resident k_enc->k_out
__device__ unsigned g_maxbits[4];              // zero-init = identity for atomicMax
__device__ unsigned g_bmin[32] = {             // identity for atomicMin (order-preserving enc)
    0xFFFFFFFFu,0xFFFFFFFFu,0xFFFFFFFFu,0xFFFFFFFFu,0xFFFFFFFFu,0xFFFFFFFFu,0xFFFFFFFFu,0xFFFFFFFFu,
    0xFFFFFFFFu,0xFFFFFFFFu,0xFFFFFFFFu,0xFFFFFFFFu,0xFFFFFFFFu,0xFFFFFFFFu,0xFFFFFFFFu,0xFFFFFFFFu,
    0xFFFFFFFFu,0xFFFFFFFFu,0xFFFFFFFFu,0xFFFFFFFFu,0xFFFFFFFFu,0xFFFFFFFFu,0xFFFFFFFFu,0xFFFFFFFFu,
    0xFFFFFFFFu,0xFFFFFFFFu,0xFFFFFFFFu,0xFFFFFFFFu,0xFFFFFFFFu,0xFFFFFFFFu,0xFFFFFFFFu,0xFFFFFFFFu};
__device__ unsigned g_bmax[32];                // zero-init = identity for atomicMax
__device__ unsigned g_dummy;                   // sink for img warm loads

__device__ __forceinline__ unsigned h2_bits(__half2 h) {
    return *reinterpret_cast<unsigned*>(&h);
}

// ---------------- Threefry-2x32 (exactly JAX's schedule) ----------------
__host__ __device__ __forceinline__ void tf2x32(unsigned k0, unsigned k1,
                                                unsigned x0, unsigned x1,
                                                unsigned &o0, unsigned &o1) {
    unsigned ks2 = k0 ^ k1 ^ 0x1BD11BDAu;
    x0 += k0; x1 += k1;
#if defined(__CUDA_ARCH__)
#define ROTL(x, r) __funnelshift_l((x), (x), (r))
#else
#define ROTL(x, r) (((x) << (r)) | ((x) >> (32 - (r))))
#endif
#define TFR(r) { x0 += x1; x1 = ROTL(x1, r); x1 ^= x0; }
    TFR(13) TFR(15) TFR(26) TFR(6)
    x0 += k1;  x1 += ks2 + 1u;
    TFR(17) TFR(29) TFR(16) TFR(24)
    x0 += ks2; x1 += k0 + 2u;
    TFR(13) TFR(15) TFR(26) TFR(6)
    x0 += k0;  x1 += k1 + 3u;
    TFR(17) TFR(29) TFR(16) TFR(24)
    x0 += k1;  x1 += ks2 + 4u;
    TFR(13) TFR(15) TFR(26) TFR(6)
    x0 += ks2; x1 += k0 + 5u;
#undef TFR
#undef ROTL
    o0 = x0; o1 = x1;
}

// ---------------- erf_inv (Giles polynomial; fast-log variant, branchy) --------
__device__ __forceinline__ float erfinv_fast(float x) {
    float w = -__logf(fmaf(-x, x, 1.0f));
    float p;
    if (w < 5.0f) {
        w = w - 2.5f;
        p =                2.81022636e-08f;
        p = fmaf(p, w,     3.43273939e-07f);
        p = fmaf(p, w,    -3.5233877e-06f);
        p = fmaf(p, w,    -4.39150654e-06f);
        p = fmaf(p, w,     0.00021858087f);
        p = fmaf(p, w,    -0.00125372503f);
        p = fmaf(p, w,    -0.00417768164f);
        p = fmaf(p, w,     0.246640727f);
        p = fmaf(p, w,     1.50140941f);
    } else {
        w = sqrtf(w) - 3.0f;
        p =               -0.000200214257f;
        p = fmaf(p, w,     0.000100950558f);
        p = fmaf(p, w,     0.00134934322f);
        p = fmaf(p, w,    -0.00367342844f);
        p = fmaf(p, w,     0.00573950773f);
        p = fmaf(p, w,    -0.0076224613f);
        p = fmaf(p, w,     0.00943887047f);
        p = fmaf(p, w,     1.00167406f);
        p = fmaf(p, w,     2.83297682f);
    }
    return p * x;
}

// Order-preserving float<->uint encoding for signed min/max atomics
__device__ __forceinline__ unsigned fenc(float f) {
    unsigned u = __float_as_uint(f);
    return (u & 0x80000000u) ? ~u : (u | 0x80000000u);
}
__device__ __forceinline__ float fdec(unsigned u) {
    return __uint_as_float((u & 0x80000000u) ? (u ^ 0x80000000u) : ~u);
}

// one sample: counter i -> N(0,1) float (R14-exact math)
__device__ __forceinline__ float sample_normal(unsigned kk0, unsigned kk1, unsigned i) {
    unsigned o0, o1;
    tf2x32(kk0, kk1, 0u, i, o0, o1);
    unsigned bits = o0 ^ o1;
    unsigned mant = __umulhi(bits, 0x00800000u);           // == bits >> 9, fma pipe
    float f = __uint_as_float(mant | 0x3F800000u) - 1.0f;  // [0,1)
    float u = fmaf(f, 2.0f, LO_F);
    u = fmaxf(u, LO_F);
    return 1.41421356237f * erfinv_fast(u);
}

// thread->geometry mapping shared by k_noise / k_enc (pair p = quads 2p, 2p+1)
__device__ __forceinline__ size_t pair_ibase(unsigned p, unsigned &pl) {
    unsigned q0 = p * 2u;
    unsigned wh0 = q0 & 255u;
    unsigned hh  = (q0 >> 8) & 255u;
    pl  = q0 >> 16;
    return (size_t)pl * 262144u + (size_t)hh * 1024u + (size_t)wh0 * 2u;
}

// ---------------- K1: noise gen (quad-major, 8 samples/thread) + maxes + img warm
// grid 12288 x 256; thread p covers quads 2p, 2p+1 across all 4 subbands.
// Warm loads target pair (p | HALF_P): only the UPPER 50 MB of img gets warmed,
// so L2 footprint = noise 50 + img 50 = 100 MB < 126 MB and both survive.
// (R14 warmed all 100 MB -> 150 MB footprint -> thrash, no benefit.
//  R15 showed removing the loads collapses the 8-chain ILP schedule; keep them.)
__global__ void __launch_bounds__(256) k_noise(const float* __restrict__ img,
                                               uint4 keyA, uint4 keyB) {
    unsigned p  = blockIdx.x * 256u + threadIdx.x;
    unsigned q0 = p * 2u;

    // ---- img L2 warm (upper half only): latency hidden by 8 threefry chains ----
    unsigned pl_;
    size_t wbase = pair_ibase(p | HALF_P, pl_);
    float4 w0 = *reinterpret_cast<const float4*>(img + wbase);
    float4 w1 = *reinterpret_cast<const float4*>(img + wbase + 512u);

    // ---- 8 independent threefry chains ----
    float nLL0 = sample_normal(keyA.x, keyA.y, q0);
    float nLL1 = sample_normal(keyA.x, keyA.y, q0 + 1u);
    float nLH0 = sample_normal(keyA.z, keyA.w, q0);
    float nLH1 = sample_normal(keyA.z, keyA.w, q0 + 1u);
    float nHL0 = sample_normal(keyB.x, keyB.y, q0);
    float nHL1 = sample_normal(keyB.x, keyB.y, q0 + 1u);
    float nHH0 = sample_normal(keyB.z, keyB.w, q0);
    float nHH1 = sample_normal(keyB.z, keyB.w, q0 + 1u);

    g_noise_q[p] = make_uint4(h2_bits(__floats2half2_rn(nLL0, nLL1)),
                              h2_bits(__floats2half2_rn(nLH0, nLH1)),
                              h2_bits(__floats2half2_rn(nHL0, nHL1)),
                              h2_bits(__floats2half2_rn(nHH0, nHH1)));

    // consume warm loads with a data-dependent never-taken store (keeps LDGs live)
    float ws = (w0.x + w0.y + w0.z + w0.w) + (w1.x + w1.y + w1.z + w1.w);
    if (__float_as_uint(ws) == 0xDEADBEEFu) g_dummy = 0u;

    // ---- per-subband max reduction (shuffle tree; REDUX measured slower R16) ----
    float m0 = fmaxf(fabsf(nLL0), fabsf(nLL1));
    float m1 = fmaxf(fabsf(nLH0), fabsf(nLH1));
    float m2 = fmaxf(fabsf(nHL0), fabsf(nHL1));
    float m3 = fmaxf(fabsf(nHH0), fabsf(nHH1));
#pragma unroll
    for (int off = 16; off; off >>= 1) {
        m0 = fmaxf(m0, __shfl_xor_sync(0xFFFFFFFFu, m0, off));
        m1 = fmaxf(m1, __shfl_xor_sync(0xFFFFFFFFu, m1, off));
        m2 = fmaxf(m2, __shfl_xor_sync(0xFFFFFFFFu, m2, off));
        m3 = fmaxf(m3, __shfl_xor_sync(0xFFFFFFFFu, m3, off));
    }
    __shared__ float smx[8][4];
    int w = threadIdx.x >> 5, l = threadIdx.x & 31;
    if (l == 0) { smx[w][0] = m0; smx[w][1] = m1; smx[w][2] = m2; smx[w][3] = m3; }
    __syncthreads();
    if (threadIdx.x < 4) {
        float m = smx[0][threadIdx.x];
#pragma unroll
        for (int j = 1; j < 8; ++j) m = fmaxf(m, smx[j][threadIdx.x]);
        atomicMax(&g_maxbits[threadIdx.x], __float_as_uint(m));  // nonneg: bits monotonic
    }
}

// ---------------- K2: enc = img + idwt(noise/max); store enc fp16; batch min/max
// grid 12288 x 256; same pair mapping. img reads are last-use -> __ldcs so the
// 100 MB img stream does not evict the enc lines being written for k_out.
__global__ void __launch_bounds__(256) k_enc(const float* __restrict__ img) {
    unsigned p = blockIdx.x * 256u + threadIdx.x;
    unsigned pl;
    size_t ibase = pair_ibase(p, pl);

    float iLL = 1.0f / (__uint_as_float(g_maxbits[0]) + 1e-8f);
    float iLH = 1.0f / (__uint_as_float(g_maxbits[1]) + 1e-8f);
    float iHL = 1.0f / (__uint_as_float(g_maxbits[2]) + 1e-8f);
    float iHH = 1.0f / (__uint_as_float(g_maxbits[3]) + 1e-8f);

    uint4 nv = __ldcs(&g_noise_q[p]);      // last use: streaming load, evicts early
    float2 LL = __half22float2(*reinterpret_cast<__half2*>(&nv.x));
    float2 LH = __half22float2(*reinterpret_cast<__half2*>(&nv.y));
    float2 HL = __half22float2(*reinterpret_cast<__half2*>(&nv.z));
    float2 HH = __half22float2(*reinterpret_cast<__half2*>(&nv.w));

    float4 i0 = __ldcs(reinterpret_cast<const float4*>(img + ibase));        // a0 b0 a1 b1
    float4 i1 = __ldcs(reinterpret_cast<const float4*>(img + ibase + 512u)); // c0 d0 c1 d1

    float4 r0, r1;
    {
        float nLL = LL.x * iLL, nLH = LH.x * iLH, nHL = HL.x * iHL, nHH = HH.x * iHH;
        float s0 = nLL + nLH, s1 = nHL + nHH;
        float d0 = nLL - nLH, d1 = nHL - nHH;
        r0.x = i0.x + (s0 + s1) * 0.5f;
        r0.y = i0.y + (s0 - s1) * 0.5f;
        r1.x = i1.x + (d0 + d1) * 0.5f;
        r1.y = i1.y + (d0 - d1) * 0.5f;
    }
    {
        float nLL = LL.y * iLL, nLH = LH.y * iLH, nHL = HL.y * iHL, nHH = HH.y * iHH;
        float s0 = nLL + nLH, s1 = nHL + nHH;
        float d0 = nLL - nLH, d1 = nHL - nHH;
        r0.z = i0.z + (s0 + s1) * 0.5f;
        r0.w = i0.w + (s0 - s1) * 0.5f;
        r1.z = i1.z + (d0 + d1) * 0.5f;
        r1.w = i1.w + (d0 - d1) * 0.5f;
    }

    *reinterpret_cast<uint2*>(g_enc_h + ibase) =
        make_uint2(h2_bits(__floats2half2_rn(r0.x, r0.y)),
                   h2_bits(__floats2half2_rn(r0.z, r0.w)));
    *reinterpret_cast<uint2*>(g_enc_h + ibase + 512u) =
        make_uint2(h2_bits(__floats2half2_rn(r1.x, r1.y)),
                   h2_bits(__floats2half2_rn(r1.z, r1.w)));

    float lmin = fminf(fminf(fminf(r0.x, r0.y), fminf(r0.z, r0.w)),
                       fminf(fminf(r1.x, r1.y), fminf(r1.z, r1.w)));
    float lmax = fmaxf(fmaxf(fmaxf(r0.x, r0.y), fmaxf(r0.z, r0.w)),
                       fmaxf(fmaxf(r1.x, r1.y), fmaxf(r1.z, r1.w)));
#pragma unroll
    for (int off = 16; off; off >>= 1) {
        lmin = fminf(lmin, __shfl_xor_sync(0xFFFFFFFFu, lmin, off));
        lmax = fmaxf(lmax, __shfl_xor_sync(0xFFFFFFFFu, lmax, off));
    }
    __shared__ float smn[8], smx[8];
    int w = threadIdx.x >> 5, l = threadIdx.x & 31;
    if (l == 0) { smn[w] = lmin; smx[w] = lmax; }
    __syncthreads();
    if (threadIdx.x == 0) {
        float mn = smn[0], mx = smx[0];
#pragma unroll
        for (int j = 1; j < 8; ++j) { mn = fminf(mn, smn[j]); mx = fmaxf(mx, smx[j]); }
        int b = (int)(blockIdx.x / 384u);   // 128 blocks/plane * 3 planes/batch
        atomicMin(&g_bmin[b], fenc(mn));
        atomicMax(&g_bmax[b], fenc(mx));
    }
}

// ---------------- K3: out = (enc_h - min) * inv ; 2 float4 per thread (MLP=2) ----
__global__ void __launch_bounds__(256) k_out(float* __restrict__ out) {
    unsigned i = blockIdx.x * 256u + threadIdx.x;    // 0 .. 3145727
    const unsigned HALF = 3145728u;                  // float4 count / 2

    unsigned iA = i, iB = i + HALF;
    // 196608 float4 per batch
    int bA = (int)(iA / 196608u);
    int bB = bA + 16;

    uint2 hA = *reinterpret_cast<const uint2*>(g_enc_h + (size_t)iA * 4u);
    uint2 hB = *reinterpret_cast<const uint2*>(g_enc_h + (size_t)iB * 4u);

    float mnA = fdec(g_bmin[bA]), mxA = fdec(g_bmax[bA]);
    float invA = 1.0f / fmaxf(mxA - mnA, 1e-8f);
    float mnB = fdec(g_bmin[bB]), mxB = fdec(g_bmax[bB]);
    float invB = 1.0f / fmaxf(mxB - mnB, 1e-8f);

    float2 fA01 = __half22float2(*reinterpret_cast<__half2*>(&hA.x));
    float2 fA23 = __half22float2(*reinterpret_cast<__half2*>(&hA.y));
    float2 fB01 = __half22float2(*reinterpret_cast<__half2*>(&hB.x));
    float2 fB23 = __half22float2(*reinterpret_cast<__half2*>(&hB.y));

    float4 rA, rB;
    rA.x = (fA01.x - mnA) * invA;  rA.y = (fA01.y - mnA) * invA;
    rA.z = (fA23.x - mnA) * invA;  rA.w = (fA23.y - mnA) * invA;
    rB.x = (fB01.x - mnB) * invB;  rB.y = (fB01.y - mnB) * invB;
    rB.z = (fB23.x - mnB) * invB;  rB.w = (fB23.y - mnB) * invB;

    __stcs(reinterpret_cast<float4*>(out) + iA, rA);   // streaming store
    __stcs(reinterpret_cast<float4*>(out) + iB, rB);
}

extern "C" void kernel_launch(void* const* d_in, const int* in_sizes, int n_in,
                              void* d_out, int out_size) {
    const float* img = (const float*)d_in[0];
    float* out = (float*)d_out;

    // jax.random.split(jax.random.key(123), 4), threefry_partitionable
    unsigned keys[8];
    for (unsigned t = 0; t < 4; ++t) {
        unsigned o0, o1;
        tf2x32(0u, 123u, 0u, t, o0, o1);
        keys[2 * t] = o0; keys[2 * t + 1] = o1;
    }
    uint4 keyA = make_uint4(keys[0], keys[1], keys[2], keys[3]);
    uint4 keyB = make_uint4(keys[4], keys[5], keys[6], keys[7]);

    k_noise<<<12288, 256>>>(img, keyA, keyB);
    k_enc<<<12288, 256>>>(img);
    k_out<<<12288, 256>>>(out);
}